// round 16
// baseline (speedup 1.0000x reference)
#include <cuda_runtime.h>
#include <cuda_fp16.h>
#include <cstdint>

#define B_ 64
#define N_ 512
#define H_ 1024
#define E_ 4
#define BN_EPS 1e-5f

// GEMM tile config: CTA 128x256, 8 warps of 64x64, BK=32, 4-stage cp.async, persistent
#define BM 128
#define BNG 256
#define BKK 32
#define GT 256
#define STAGES 4
#define STAGE_BYTES 24576   // A 8K | B 16K
#define OFF_BH 8192
#define SMEM_BYTES (STAGES * STAGE_BYTES)

// prologue kernel block split
#define PRO_MEAN_BLOCKS 512                       // B_*8
#define PRO_W_BLOCKS 4096                         // E_*H_*H_/4/256
#define PRO_BLOCKS (PRO_MEAN_BLOCKS + PRO_W_BLOCKS)

// ---------------- scratch (static device globals; no allocation) ----------------
__device__ __align__(256) __half g_xh[(size_t)B_ * N_ * H_];
__device__ __align__(256) __half g_wh[(size_t)E_ * H_ * H_];
__device__ __align__(256) __half g_suph[(size_t)B_ * N_ * H_];
__device__ __align__(256) __half g_outh[(size_t)B_ * N_ * H_];
__device__ __align__(256) float g_score_part[B_ * 8 * E_];
__device__ __align__(256) float g_sum[E_ * H_];
__device__ __align__(256) float g_ss[E_ * H_];
__device__ int g_top1[B_];

// ---------------- PTX helpers (base-family ISA) ----------------
__device__ __forceinline__ uint32_t smem_u32(const void* p) {
    uint32_t a;
    asm("{ .reg .u64 t; cvta.to.shared.u64 t, %1; cvt.u32.u64 %0, t; }" : "=r"(a) : "l"(p));
    return a;
}
__device__ __forceinline__ void cp16(uint32_t d, const void* g) {
    asm volatile("cp.async.cg.shared.global [%0], [%1], 16;" :: "r"(d), "l"(g));
}
__device__ __forceinline__ void ldsm_x4(uint32_t (&r)[4], uint32_t addr) {
    asm volatile("ldmatrix.sync.aligned.m8n8.x4.shared.b16 {%0,%1,%2,%3}, [%4];"
        : "=r"(r[0]), "=r"(r[1]), "=r"(r[2]), "=r"(r[3]) : "r"(addr));
}
__device__ __forceinline__ void ldsm_x4_t(uint32_t (&r)[4], uint32_t addr) {
    asm volatile("ldmatrix.sync.aligned.m8n8.x4.trans.shared.b16 {%0,%1,%2,%3}, [%4];"
        : "=r"(r[0]), "=r"(r[1]), "=r"(r[2]), "=r"(r[3]) : "r"(addr));
}
__device__ __forceinline__ void mma_f16(float (&c)[4], const uint32_t (&a)[4], const uint32_t* b) {
    asm volatile(
        "mma.sync.aligned.m16n8k16.row.col.f32.f16.f16.f32 "
        "{%0,%1,%2,%3}, {%4,%5,%6,%7}, {%8,%9}, {%0,%1,%2,%3};"
        : "+f"(c[0]), "+f"(c[1]), "+f"(c[2]), "+f"(c[3])
        : "r"(a[0]), "r"(a[1]), "r"(a[2]), "r"(a[3]), "r"(b[0]), "r"(b[1]));
}

// ---------------- k1: fused prologue ----------------
// blocks [0, 512):    x -> fp16 + router score partials
// blocks [512, 4608): expert_w -> fp16 + stats zeroing
__global__ void prologue_kernel(const float* __restrict__ x, const float* __restrict__ rw,
                                const float* __restrict__ w_src) {
    if (blockIdx.x < PRO_MEAN_BLOCKS) {
        int b = blockIdx.x >> 3, s = blockIdx.x & 7;
        size_t base = (size_t)b * N_ * H_ + (size_t)s * 64 * H_;
        const float* xb = x + base;
        __half* xh = g_xh + base;
        __shared__ float sred[E_][256];
        float se[E_] = {0.f, 0.f, 0.f, 0.f};
        for (int h = threadIdx.x; h < H_; h += blockDim.x) {
            float acc = 0.f;
            #pragma unroll 8
            for (int n = 0; n < 64; n++) {
                float v = xb[(size_t)n * H_ + h];
                xh[(size_t)n * H_ + h] = __float2half_rn(v);
                acc += v;
            }
            #pragma unroll
            for (int e = 0; e < E_; e++) se[e] += acc * rw[h * E_ + e];
        }
        #pragma unroll
        for (int e = 0; e < E_; e++) sred[e][threadIdx.x] = se[e];
        __syncthreads();
        for (int off = 128; off > 0; off >>= 1) {
            if (threadIdx.x < off) {
                #pragma unroll
                for (int e = 0; e < E_; e++) sred[e][threadIdx.x] += sred[e][threadIdx.x + off];
            }
            __syncthreads();
        }
        if (threadIdx.x < E_) g_score_part[(b * 8 + s) * E_ + threadIdx.x] = sred[threadIdx.x][0];
    } else {
        size_t t = (size_t)(blockIdx.x - PRO_MEAN_BLOCKS) * blockDim.x + threadIdx.x;
        if (t < E_ * H_) { g_sum[t] = 0.f; g_ss[t] = 0.f; }
        size_t i = t * 4;
        float4 v = *(const float4*)(w_src + i);
        *(__half2*)(g_wh + i) = __floats2half2_rn(v.x, v.y);
        *(__half2*)(g_wh + i + 2) = __floats2half2_rn(v.z, v.w);
    }
}

// ---------------- k2: argmax over summed partials ----------
__global__ void argmax_kernel(const float* __restrict__ rb) {
    int b = threadIdx.x;   // 64 threads
    float sc[E_];
    #pragma unroll
    for (int e = 0; e < E_; e++) sc[e] = rb[e] * (float)N_;   // compare N*score (monotone)
    for (int s = 0; s < 8; s++)
        #pragma unroll
        for (int e = 0; e < E_; e++) sc[e] += g_score_part[(b * 8 + s) * E_ + e];
    int best = 0;
    float bv = sc[0];
    for (int e = 1; e < E_; e++)
        if (sc[e] > bv) { bv = sc[e]; best = e; }
    g_top1[b] = best;
}

// ---------------- persistent batched fp16 mma GEMM ----------------
// AFP32=0: A is fp16, loaded via cp.async (gemm1 path)
// AFP32=1: A is fp32, loaded via LDG + in-register cvt + STS (gemm2: adj direct)
// fp16 output; withStats adds fused per-expert BN statistics
template <int AFP32>
__global__ __launch_bounds__(GT, 1)
void gemm_f16_kernel(const void* __restrict__ Abase, long strideA, int lda,
                     const __half* __restrict__ Bbase, long strideB, int ldb, int useTop1,
                     __half* __restrict__ Ch, int withStats,
                     long strideC, int ldc, int K, int nTilesN, int nTilesTotal) {
    extern __shared__ __align__(128) char smem[];
    const uint32_t sb = smem_u32(smem);
    const int tid = threadIdx.x;
    const int lane = tid & 31, wid = tid >> 5;
    const int wm = (wid >> 2) * 64, wn = (wid & 3) * 64;
    const int tilesPerB = nTilesN * (N_ / BM);

    const int ar = tid >> 1, ac0 = (tid & 1) * 2;
    const int bk = tid >> 3, bn0 = (tid & 7) * 4;
    uint32_t a_off[2], b_off[4];
    #pragma unroll
    for (int q = 0; q < 2; q++) {
        int c = ac0 + q;
        a_off[q] = (uint32_t)(ar * 64 + ((c ^ ((ar >> 1) & 3)) << 4));
    }
    #pragma unroll
    for (int q = 0; q < 4; q++) {
        int nc = bn0 + q;
        b_off[q] = (uint32_t)((nc >> 4) * 8192 + bk * 256 + (((nc & 15) ^ (bk & 7)) << 4));
    }

    const int nk = K / BKK;

    for (int t = blockIdx.x; t < nTilesTotal; t += gridDim.x) {
        const int bz = t / tilesPerB;
        const int r = t - bz * tilesPerB;
        const int n0 = (r % nTilesN) * BNG;
        const int m0 = (r / nTilesN) * BM;

        const int sel = useTop1 ? g_top1[bz] : bz;
        const __half* Bg = Bbase + (long)sel * strideB;
        const __half* b_g = Bg + (long)bk * ldb + n0 + bn0 * 8;
        const __half* a_gh = nullptr;
        const float* a_gf = nullptr;
        if (AFP32)
            a_gf = (const float*)Abase + (long)bz * strideA + (long)(m0 + ar) * lda + ac0 * 8;
        else
            a_gh = (const __half*)Abase + (long)bz * strideA + (long)(m0 + ar) * lda + ac0 * 8;

        float acc[4][8][4];
        #pragma unroll
        for (int a = 0; a < 4; a++)
            #pragma unroll
            for (int b2 = 0; b2 < 8; b2++)
                #pragma unroll
                for (int c = 0; c < 4; c++) acc[a][b2][c] = 0.f;

        float areg[16];

        auto ldgA = [&](int i) {
            const float4* p = (const float4*)(a_gf + (long)i * BKK);
            #pragma unroll
            for (int q = 0; q < 4; q++) *(float4*)&areg[q * 4] = p[q];
        };
        auto stsA = [&](int i) {
            char* st = smem + (i & (STAGES - 1)) * STAGE_BYTES;
            #pragma unroll
            for (int q = 0; q < 2; q++) {
                uint4 hw;
                uint32_t* hwp = (uint32_t*)&hw;
                #pragma unroll
                for (int j = 0; j < 4; j++) {
                    __half2 h2 = __floats2half2_rn(areg[q * 8 + 2 * j], areg[q * 8 + 2 * j + 1]);
                    hwp[j] = *(uint32_t*)&h2;
                }
                *(uint4*)(st + a_off[q]) = hw;
            }
        };
        auto issueB = [&](int i) {
            uint32_t st = sb + (uint32_t)((i & (STAGES - 1)) * STAGE_BYTES);
            if (!AFP32) {
                const __half* ag = a_gh + (long)i * BKK;
                #pragma unroll
                for (int q = 0; q < 2; q++) cp16(st + a_off[q], ag + q * 8);
            }
            const __half* bg = b_g + (long)i * BKK * ldb;
            #pragma unroll
            for (int q = 0; q < 4; q++) cp16(st + OFF_BH + b_off[q], bg + q * 8);
            asm volatile("cp.async.commit_group;" ::: "memory");
        };

        auto mma_tile = [&](int s) {
            const uint32_t aB = sb + (uint32_t)(s * STAGE_BYTES);
            #pragma unroll
            for (int ks = 0; ks < 2; ks++) {
                uint32_t ahf[4][4];
                #pragma unroll
                for (int mt = 0; mt < 4; mt++) {
                    int rr = wm + mt * 16 + (lane & 15);
                    int c = ks * 2 + (lane >> 4);
                    ldsm_x4(ahf[mt], aB + (uint32_t)(rr * 64 + ((c ^ ((rr >> 1) & 3)) << 4)));
                }
                int k = ks * 16 + (lane & 15);
                #pragma unroll
                for (int nt = 0; nt < 4; nt++) {
                    int nl = wn + nt * 16 + ((lane >> 4) << 3);
                    uint32_t boff = (uint32_t)((nl >> 7) * 8192 + k * 256 +
                                               ((((nl & 127) >> 3) ^ (k & 7)) << 4));
                    uint32_t r4[4];
                    ldsm_x4_t(r4, aB + OFF_BH + boff);
                    #pragma unroll
                    for (int mt = 0; mt < 4; mt++) {
                        mma_f16(acc[mt][nt * 2], ahf[mt], r4);
                        mma_f16(acc[mt][nt * 2 + 1], ahf[mt], r4 + 2);
                    }
                }
            }
        };

        if (AFP32) {
            ldgA(0); stsA(0); issueB(0);
            ldgA(1); stsA(1); issueB(1);
            ldgA(2); stsA(2); issueB(2);
            ldgA(3);
        } else {
            issueB(0); issueB(1); issueB(2);
        }
        for (int i = 0; i < nk; i++) {
            asm volatile("cp.async.wait_group 2;" ::: "memory");
            __syncthreads();
            mma_tile(i & (STAGES - 1));
            if (i + 3 < nk) {
                if (AFP32) {
                    stsA(i + 3);
                    issueB(i + 3);
                    if (i + 4 < nk) ldgA(i + 4);
                } else {
                    issueB(i + 3);
                }
            } else {
                asm volatile("cp.async.commit_group;" ::: "memory");
            }
        }
        asm volatile("cp.async.wait_all;" ::: "memory");

        __half* CH = Ch + (long)bz * strideC;
        #pragma unroll
        for (int mt = 0; mt < 4; mt++) {
            int row0 = m0 + wm + mt * 16 + (lane >> 2);
            #pragma unroll
            for (int n8 = 0; n8 < 8; n8++) {
                int col = n0 + wn + n8 * 8 + (lane & 3) * 2;
                *(__half2*)(CH + (long)row0 * ldc + col) =
                    __floats2half2_rn(acc[mt][n8][0], acc[mt][n8][1]);
                *(__half2*)(CH + (long)(row0 + 8) * ldc + col) =
                    __floats2half2_rn(acc[mt][n8][2], acc[mt][n8][3]);
            }
        }
        if (withStats) {
            int e = g_top1[bz];
            #pragma unroll
            for (int n8 = 0; n8 < 8; n8++) {
                #pragma unroll
                for (int c2 = 0; c2 < 2; c2++) {
                    float s = 0.f, q = 0.f;
                    #pragma unroll
                    for (int mt = 0; mt < 4; mt++) {
                        float v0 = acc[mt][n8][c2], v1 = acc[mt][n8][c2 + 2];
                        s += v0 + v1;
                        q += v0 * v0 + v1 * v1;
                    }
                    s += __shfl_xor_sync(0xFFFFFFFFu, s, 4);
                    q += __shfl_xor_sync(0xFFFFFFFFu, q, 4);
                    s += __shfl_xor_sync(0xFFFFFFFFu, s, 8);
                    q += __shfl_xor_sync(0xFFFFFFFFu, q, 8);
                    s += __shfl_xor_sync(0xFFFFFFFFu, s, 16);
                    q += __shfl_xor_sync(0xFFFFFFFFu, q, 16);
                    if ((lane >> 2) == 0) {
                        int col = n0 + wn + n8 * 8 + (lane & 3) * 2 + c2;
                        atomicAdd(&g_sum[e * H_ + col], s);
                        atomicAdd(&g_ss[e * H_ + col], q);
                    }
                }
            }
        }
        __syncthreads();
    }
}

// ---------------- k7: BN finalize + apply + ReLU (fp16 in, fp32 out), fused ----------
__global__ void bn_relu_kernel(float* __restrict__ out,
                               const float* __restrict__ gamma, const float* __restrict__ beta) {
    __shared__ int scnt[E_];
    if (threadIdx.x < E_) {
        int e = threadIdx.x, cg = 0;
        for (int b = 0; b < B_; b++) cg += (g_top1[b] == e);
        scnt[e] = cg;
    }
    __syncthreads();

    size_t idx = ((size_t)blockIdx.x * blockDim.x + threadIdx.x) * 4;
    int b = (int)(idx / ((size_t)N_ * H_));
    int h = (int)(idx % H_);
    int e = g_top1[b];
    float cnt = fmaxf((float)scnt[e] * (float)N_, 1.0f);

    float4 s4 = *(const float4*)&g_sum[e * H_ + h];
    float4 q4 = *(const float4*)&g_ss[e * H_ + h];
    float4 g4 = *(const float4*)&gamma[e * H_ + h];
    float4 b4 = *(const float4*)&beta[e * H_ + h];

    __half2 i0 = *(const __half2*)(g_outh + idx);
    __half2 i1 = *(const __half2*)(g_outh + idx + 2);
    float4 v = make_float4(__half2float(i0.x), __half2float(i0.y),
                           __half2float(i1.x), __half2float(i1.y));

    float m, var, inv, sc, sh;
    m = s4.x / cnt; var = q4.x / cnt - m * m; inv = rsqrtf(var + BN_EPS);
    sc = g4.x * inv; sh = b4.x - m * sc; v.x = fmaxf(v.x * sc + sh, 0.f);
    m = s4.y / cnt; var = q4.y / cnt - m * m; inv = rsqrtf(var + BN_EPS);
    sc = g4.y * inv; sh = b4.y - m * sc; v.y = fmaxf(v.y * sc + sh, 0.f);
    m = s4.z / cnt; var = q4.z / cnt - m * m; inv = rsqrtf(var + BN_EPS);
    sc = g4.z * inv; sh = b4.z - m * sc; v.z = fmaxf(v.z * sc + sh, 0.f);
    m = s4.w / cnt; var = q4.w / cnt - m * m; inv = rsqrtf(var + BN_EPS);
    sc = g4.w * inv; sh = b4.w - m * sc; v.w = fmaxf(v.w * sc + sh, 0.f);

    *(float4*)(out + idx) = v;
}

// ---------------- launcher (single stream, serial) ----------------
extern "C" void kernel_launch(void* const* d_in, const int* in_sizes, int n_in,
                              void* d_out, int out_size) {
    (void)in_sizes; (void)n_in; (void)out_size;
    const float* x        = (const float*)d_in[0];   // [B,N,H]
    const float* adj      = (const float*)d_in[1];   // [B,N,N]
    const float* router_w = (const float*)d_in[2];   // [H,E]
    const float* router_b = (const float*)d_in[3];   // [E]
    const float* expert_w = (const float*)d_in[4];   // [E,H,H]
    const float* bn_gamma = (const float*)d_in[5];   // [E,H]
    const float* bn_beta  = (const float*)d_in[6];   // [E,H]
    float* out = (float*)d_out;                      // [B,N,H]

    __half *xh, *wh, *suph, *outh;
    cudaGetSymbolAddress((void**)&xh, g_xh);
    cudaGetSymbolAddress((void**)&wh, g_wh);
    cudaGetSymbolAddress((void**)&suph, g_suph);
    cudaGetSymbolAddress((void**)&outh, g_outh);

    static int nsm = 0;
    if (!nsm) {
        int dev = 0;
        cudaGetDevice(&dev);
        cudaDeviceGetAttribute(&nsm, cudaDevAttrMultiProcessorCount, dev);
        if (nsm <= 0) nsm = 148;
        cudaFuncSetAttribute(gemm_f16_kernel<0>, cudaFuncAttributeMaxDynamicSharedMemorySize, SMEM_BYTES);
        cudaFuncSetAttribute(gemm_f16_kernel<1>, cudaFuncAttributeMaxDynamicSharedMemorySize, SMEM_BYTES);
    }

    prologue_kernel<<<PRO_BLOCKS, 256>>>(x, router_w, expert_w);
    argmax_kernel<<<1, B_>>>(router_b);

    const int nTilesN = H_ / BNG;                            // 4
    const int nTilesTotal = nTilesN * (N_ / BM) * B_;        // 1024

    // support[b] = x[b] @ expert_w[top1[b]]  -> fp16  (A fp16 cp.async)
    gemm_f16_kernel<0><<<nsm, GT, SMEM_BYTES>>>(
        xh, (long)N_ * H_, H_,
        wh, (long)H_ * H_, H_, 1,
        suph, 0, (long)N_ * H_, H_, H_, nTilesN, nTilesTotal);

    // outh[b] = adj[b] @ support[b]  -> fp16 + fused stats  (A fp32 in-kernel cvt)
    gemm_f16_kernel<1><<<nsm, GT, SMEM_BYTES>>>(
        adj, (long)N_ * N_, N_,
        suph, (long)N_ * H_, H_, 0,
        outh, 1, (long)N_ * H_, H_, N_, nTilesN, nTilesTotal);

    size_t total4 = (size_t)B_ * N_ * H_ / 4;
    bn_relu_kernel<<<(unsigned)(total4 / 256), 256>>>(out, bn_gamma, bn_beta);
}

// round 17
// speedup vs baseline: 1.0745x; 1.0745x over previous
#include <cuda_runtime.h>
#include <cuda_fp16.h>
#include <cstdint>

#define B_ 64
#define N_ 512
#define H_ 1024
#define E_ 4
#define BN_EPS 1e-5f

// GEMM tile config: CTA 128x256, 8 warps of 64x64, BK=32, 4-stage cp.async, persistent
#define BM 128
#define BNG 256
#define BKK 32
#define GT 256
#define STAGES 4
#define STAGE_BYTES 24576   // A 8K | B 16K
#define OFF_BH 8192
#define SMEM_BYTES (STAGES * STAGE_BYTES)

// prologue kernel block split
#define PRO_MEAN_BLOCKS 512                       // B_*8
#define PRO_W_BLOCKS 4096                         // E_*H_*H_/4/256
#define PRO_BLOCKS (PRO_MEAN_BLOCKS + PRO_W_BLOCKS)

// ---------------- scratch (static device globals; no allocation) ----------------
__device__ __align__(256) __half g_xh[(size_t)B_ * N_ * H_];
__device__ __align__(256) __half g_wh[(size_t)E_ * H_ * H_];
__device__ __align__(256) __half g_suph[(size_t)B_ * N_ * H_];
__device__ __align__(256) __half g_outh[(size_t)B_ * N_ * H_];
__device__ __align__(256) float g_score_part[B_ * 8 * E_];
__device__ __align__(256) float g_sum[E_ * H_];
__device__ __align__(256) float g_ss[E_ * H_];
__device__ __align__(256) float g_scale[E_ * H_];
__device__ __align__(256) float g_shift[E_ * H_];
__device__ int g_top1[B_];

// ---------------- PTX helpers (base-family ISA) ----------------
__device__ __forceinline__ uint32_t smem_u32(const void* p) {
    uint32_t a;
    asm("{ .reg .u64 t; cvta.to.shared.u64 t, %1; cvt.u32.u64 %0, t; }" : "=r"(a) : "l"(p));
    return a;
}
__device__ __forceinline__ void cp16(uint32_t d, const void* g) {
    asm volatile("cp.async.cg.shared.global [%0], [%1], 16;" :: "r"(d), "l"(g));
}
__device__ __forceinline__ void ldsm_x4(uint32_t (&r)[4], uint32_t addr) {
    asm volatile("ldmatrix.sync.aligned.m8n8.x4.shared.b16 {%0,%1,%2,%3}, [%4];"
        : "=r"(r[0]), "=r"(r[1]), "=r"(r[2]), "=r"(r[3]) : "r"(addr));
}
__device__ __forceinline__ void ldsm_x4_t(uint32_t (&r)[4], uint32_t addr) {
    asm volatile("ldmatrix.sync.aligned.m8n8.x4.trans.shared.b16 {%0,%1,%2,%3}, [%4];"
        : "=r"(r[0]), "=r"(r[1]), "=r"(r[2]), "=r"(r[3]) : "r"(addr));
}
__device__ __forceinline__ void mma_f16(float (&c)[4], const uint32_t (&a)[4], const uint32_t* b) {
    asm volatile(
        "mma.sync.aligned.m16n8k16.row.col.f32.f16.f16.f32 "
        "{%0,%1,%2,%3}, {%4,%5,%6,%7}, {%8,%9}, {%0,%1,%2,%3};"
        : "+f"(c[0]), "+f"(c[1]), "+f"(c[2]), "+f"(c[3])
        : "r"(a[0]), "r"(a[1]), "r"(a[2]), "r"(a[3]), "r"(b[0]), "r"(b[1]));
}

// ---------------- k1: fused prologue ----------------
// blocks [0, 512):    x -> fp16 + router score partials
// blocks [512, 4608): expert_w -> fp16 + stats zeroing
__global__ void prologue_kernel(const float* __restrict__ x, const float* __restrict__ rw,
                                const float* __restrict__ w_src) {
    if (blockIdx.x < PRO_MEAN_BLOCKS) {
        int b = blockIdx.x >> 3, s = blockIdx.x & 7;
        size_t base = (size_t)b * N_ * H_ + (size_t)s * 64 * H_;
        const float* xb = x + base;
        __half* xh = g_xh + base;
        __shared__ float sred[E_][256];
        float se[E_] = {0.f, 0.f, 0.f, 0.f};
        for (int h = threadIdx.x; h < H_; h += blockDim.x) {
            float acc = 0.f;
            #pragma unroll 8
            for (int n = 0; n < 64; n++) {
                float v = xb[(size_t)n * H_ + h];
                xh[(size_t)n * H_ + h] = __float2half_rn(v);
                acc += v;
            }
            #pragma unroll
            for (int e = 0; e < E_; e++) se[e] += acc * rw[h * E_ + e];
        }
        #pragma unroll
        for (int e = 0; e < E_; e++) sred[e][threadIdx.x] = se[e];
        __syncthreads();
        for (int off = 128; off > 0; off >>= 1) {
            if (threadIdx.x < off) {
                #pragma unroll
                for (int e = 0; e < E_; e++) sred[e][threadIdx.x] += sred[e][threadIdx.x + off];
            }
            __syncthreads();
        }
        if (threadIdx.x < E_) g_score_part[(b * 8 + s) * E_ + threadIdx.x] = sred[threadIdx.x][0];
    } else {
        size_t t = (size_t)(blockIdx.x - PRO_MEAN_BLOCKS) * blockDim.x + threadIdx.x;
        if (t < E_ * H_) { g_sum[t] = 0.f; g_ss[t] = 0.f; }
        size_t i = t * 4;
        float4 v = *(const float4*)(w_src + i);
        *(__half2*)(g_wh + i) = __floats2half2_rn(v.x, v.y);
        *(__half2*)(g_wh + i + 2) = __floats2half2_rn(v.z, v.w);
    }
}

// ---------------- k2: argmax over summed partials ----------
__global__ void argmax_kernel(const float* __restrict__ rb) {
    int b = threadIdx.x;   // 64 threads
    float sc[E_];
    #pragma unroll
    for (int e = 0; e < E_; e++) sc[e] = rb[e] * (float)N_;   // compare N*score (monotone)
    for (int s = 0; s < 8; s++)
        #pragma unroll
        for (int e = 0; e < E_; e++) sc[e] += g_score_part[(b * 8 + s) * E_ + e];
    int best = 0;
    float bv = sc[0];
    for (int e = 1; e < E_; e++)
        if (sc[e] > bv) { bv = sc[e]; best = e; }
    g_top1[b] = best;
}

// ---------------- persistent batched fp16 mma GEMM ----------------
// AFP32=0: A is fp16, loaded via cp.async (gemm1 path)
// AFP32=1: A is fp32, loaded via LDG + in-register cvt + STS (gemm2: adj direct)
// fp16 output; withStats adds fused per-expert BN statistics
template <int AFP32>
__global__ __launch_bounds__(GT, 1)
void gemm_f16_kernel(const void* __restrict__ Abase, long strideA, int lda,
                     const __half* __restrict__ Bbase, long strideB, int ldb, int useTop1,
                     __half* __restrict__ Ch, int withStats,
                     long strideC, int ldc, int K, int nTilesN, int nTilesTotal) {
    extern __shared__ __align__(128) char smem[];
    const uint32_t sb = smem_u32(smem);
    const int tid = threadIdx.x;
    const int lane = tid & 31, wid = tid >> 5;
    const int wm = (wid >> 2) * 64, wn = (wid & 3) * 64;
    const int tilesPerB = nTilesN * (N_ / BM);

    const int ar = tid >> 1, ac0 = (tid & 1) * 2;
    const int bk = tid >> 3, bn0 = (tid & 7) * 4;
    uint32_t a_off[2], b_off[4];
    #pragma unroll
    for (int q = 0; q < 2; q++) {
        int c = ac0 + q;
        a_off[q] = (uint32_t)(ar * 64 + ((c ^ ((ar >> 1) & 3)) << 4));
    }
    #pragma unroll
    for (int q = 0; q < 4; q++) {
        int nc = bn0 + q;
        b_off[q] = (uint32_t)((nc >> 4) * 8192 + bk * 256 + (((nc & 15) ^ (bk & 7)) << 4));
    }

    const int nk = K / BKK;

    for (int t = blockIdx.x; t < nTilesTotal; t += gridDim.x) {
        const int bz = t / tilesPerB;
        const int r = t - bz * tilesPerB;
        const int n0 = (r % nTilesN) * BNG;
        const int m0 = (r / nTilesN) * BM;

        const int sel = useTop1 ? g_top1[bz] : bz;
        const __half* Bg = Bbase + (long)sel * strideB;
        const __half* b_g = Bg + (long)bk * ldb + n0 + bn0 * 8;
        const __half* a_gh = nullptr;
        const float* a_gf = nullptr;
        if (AFP32)
            a_gf = (const float*)Abase + (long)bz * strideA + (long)(m0 + ar) * lda + ac0 * 8;
        else
            a_gh = (const __half*)Abase + (long)bz * strideA + (long)(m0 + ar) * lda + ac0 * 8;

        float acc[4][8][4];
        #pragma unroll
        for (int a = 0; a < 4; a++)
            #pragma unroll
            for (int b2 = 0; b2 < 8; b2++)
                #pragma unroll
                for (int c = 0; c < 4; c++) acc[a][b2][c] = 0.f;

        float areg[16];

        auto ldgA = [&](int i) {
            const float4* p = (const float4*)(a_gf + (long)i * BKK);
            #pragma unroll
            for (int q = 0; q < 4; q++) *(float4*)&areg[q * 4] = p[q];
        };
        auto stsA = [&](int i) {
            char* st = smem + (i & (STAGES - 1)) * STAGE_BYTES;
            #pragma unroll
            for (int q = 0; q < 2; q++) {
                uint4 hw;
                uint32_t* hwp = (uint32_t*)&hw;
                #pragma unroll
                for (int j = 0; j < 4; j++) {
                    __half2 h2 = __floats2half2_rn(areg[q * 8 + 2 * j], areg[q * 8 + 2 * j + 1]);
                    hwp[j] = *(uint32_t*)&h2;
                }
                *(uint4*)(st + a_off[q]) = hw;
            }
        };
        auto issueB = [&](int i) {
            uint32_t st = sb + (uint32_t)((i & (STAGES - 1)) * STAGE_BYTES);
            if (!AFP32) {
                const __half* ag = a_gh + (long)i * BKK;
                #pragma unroll
                for (int q = 0; q < 2; q++) cp16(st + a_off[q], ag + q * 8);
            }
            const __half* bg = b_g + (long)i * BKK * ldb;
            #pragma unroll
            for (int q = 0; q < 4; q++) cp16(st + OFF_BH + b_off[q], bg + q * 8);
            asm volatile("cp.async.commit_group;" ::: "memory");
        };

        auto mma_tile = [&](int s) {
            const uint32_t aB = sb + (uint32_t)(s * STAGE_BYTES);
            #pragma unroll
            for (int ks = 0; ks < 2; ks++) {
                uint32_t ahf[4][4];
                #pragma unroll
                for (int mt = 0; mt < 4; mt++) {
                    int rr = wm + mt * 16 + (lane & 15);
                    int c = ks * 2 + (lane >> 4);
                    ldsm_x4(ahf[mt], aB + (uint32_t)(rr * 64 + ((c ^ ((rr >> 1) & 3)) << 4)));
                }
                int k = ks * 16 + (lane & 15);
                #pragma unroll
                for (int nt = 0; nt < 4; nt++) {
                    int nl = wn + nt * 16 + ((lane >> 4) << 3);
                    uint32_t boff = (uint32_t)((nl >> 7) * 8192 + k * 256 +
                                               ((((nl & 127) >> 3) ^ (k & 7)) << 4));
                    uint32_t r4[4];
                    ldsm_x4_t(r4, aB + OFF_BH + boff);
                    #pragma unroll
                    for (int mt = 0; mt < 4; mt++) {
                        mma_f16(acc[mt][nt * 2], ahf[mt], r4);
                        mma_f16(acc[mt][nt * 2 + 1], ahf[mt], r4 + 2);
                    }
                }
            }
        };

        if (AFP32) {
            ldgA(0); stsA(0); issueB(0);
            ldgA(1); stsA(1); issueB(1);
            ldgA(2); stsA(2); issueB(2);
            ldgA(3);
        } else {
            issueB(0); issueB(1); issueB(2);
        }
        for (int i = 0; i < nk; i++) {
            asm volatile("cp.async.wait_group 2;" ::: "memory");
            __syncthreads();
            mma_tile(i & (STAGES - 1));
            if (i + 3 < nk) {
                if (AFP32) {
                    stsA(i + 3);
                    issueB(i + 3);
                    if (i + 4 < nk) ldgA(i + 4);
                } else {
                    issueB(i + 3);
                }
            } else {
                asm volatile("cp.async.commit_group;" ::: "memory");
            }
        }
        asm volatile("cp.async.wait_all;" ::: "memory");

        __half* CH = Ch + (long)bz * strideC;
        #pragma unroll
        for (int mt = 0; mt < 4; mt++) {
            int row0 = m0 + wm + mt * 16 + (lane >> 2);
            #pragma unroll
            for (int n8 = 0; n8 < 8; n8++) {
                int col = n0 + wn + n8 * 8 + (lane & 3) * 2;
                *(__half2*)(CH + (long)row0 * ldc + col) =
                    __floats2half2_rn(acc[mt][n8][0], acc[mt][n8][1]);
                *(__half2*)(CH + (long)(row0 + 8) * ldc + col) =
                    __floats2half2_rn(acc[mt][n8][2], acc[mt][n8][3]);
            }
        }
        if (withStats) {
            int e = g_top1[bz];
            #pragma unroll
            for (int n8 = 0; n8 < 8; n8++) {
                #pragma unroll
                for (int c2 = 0; c2 < 2; c2++) {
                    float s = 0.f, q = 0.f;
                    #pragma unroll
                    for (int mt = 0; mt < 4; mt++) {
                        float v0 = acc[mt][n8][c2], v1 = acc[mt][n8][c2 + 2];
                        s += v0 + v1;
                        q += v0 * v0 + v1 * v1;
                    }
                    s += __shfl_xor_sync(0xFFFFFFFFu, s, 4);
                    q += __shfl_xor_sync(0xFFFFFFFFu, q, 4);
                    s += __shfl_xor_sync(0xFFFFFFFFu, s, 8);
                    q += __shfl_xor_sync(0xFFFFFFFFu, q, 8);
                    s += __shfl_xor_sync(0xFFFFFFFFu, s, 16);
                    q += __shfl_xor_sync(0xFFFFFFFFu, q, 16);
                    if ((lane >> 2) == 0) {
                        int col = n0 + wn + n8 * 8 + (lane & 3) * 2 + c2;
                        atomicAdd(&g_sum[e * H_ + col], s);
                        atomicAdd(&g_ss[e * H_ + col], q);
                    }
                }
            }
        }
        __syncthreads();
    }
}

// ---------------- k6: finalize BN scale/shift ----------
__global__ void finalize_kernel(const float* __restrict__ gamma, const float* __restrict__ beta) {
    int e = blockIdx.x, h = threadIdx.x;
    int cg = 0;
    for (int b = 0; b < B_; b++) cg += (g_top1[b] == e);
    float cnt = fmaxf((float)cg * (float)N_, 1.0f);
    float mean = g_sum[e * H_ + h] / cnt;
    float var = g_ss[e * H_ + h] / cnt - mean * mean;
    float inv = rsqrtf(var + BN_EPS);
    float sc = gamma[e * H_ + h] * inv;
    g_scale[e * H_ + h] = sc;
    g_shift[e * H_ + h] = beta[e * H_ + h] - mean * sc;
}

// ---------------- k7: apply BN + ReLU (fp16 in, fp32 out) ----------
__global__ void bn_relu_kernel(float* __restrict__ out) {
    size_t idx = ((size_t)blockIdx.x * blockDim.x + threadIdx.x) * 4;
    int b = (int)(idx / ((size_t)N_ * H_));
    int h = (int)(idx % H_);
    int e = g_top1[b];
    __half2 i0 = *(const __half2*)(g_outh + idx);
    __half2 i1 = *(const __half2*)(g_outh + idx + 2);
    float4 v = make_float4(__half2float(i0.x), __half2float(i0.y),
                           __half2float(i1.x), __half2float(i1.y));
    float4 sc = *(const float4*)&g_scale[e * H_ + h];
    float4 sh = *(const float4*)&g_shift[e * H_ + h];
    v.x = fmaxf(v.x * sc.x + sh.x, 0.f);
    v.y = fmaxf(v.y * sc.y + sh.y, 0.f);
    v.z = fmaxf(v.z * sc.z + sh.z, 0.f);
    v.w = fmaxf(v.w * sc.w + sh.w, 0.f);
    *(float4*)(out + idx) = v;
}

// ---------------- launcher (single stream, serial) ----------------
extern "C" void kernel_launch(void* const* d_in, const int* in_sizes, int n_in,
                              void* d_out, int out_size) {
    (void)in_sizes; (void)n_in; (void)out_size;
    const float* x        = (const float*)d_in[0];   // [B,N,H]
    const float* adj      = (const float*)d_in[1];   // [B,N,N]
    const float* router_w = (const float*)d_in[2];   // [H,E]
    const float* router_b = (const float*)d_in[3];   // [E]
    const float* expert_w = (const float*)d_in[4];   // [E,H,H]
    const float* bn_gamma = (const float*)d_in[5];   // [E,H]
    const float* bn_beta  = (const float*)d_in[6];   // [E,H]
    float* out = (float*)d_out;                      // [B,N,H]

    __half *xh, *wh, *suph, *outh;
    cudaGetSymbolAddress((void**)&xh, g_xh);
    cudaGetSymbolAddress((void**)&wh, g_wh);
    cudaGetSymbolAddress((void**)&suph, g_suph);
    cudaGetSymbolAddress((void**)&outh, g_outh);

    static int nsm = 0;
    if (!nsm) {
        int dev = 0;
        cudaGetDevice(&dev);
        cudaDeviceGetAttribute(&nsm, cudaDevAttrMultiProcessorCount, dev);
        if (nsm <= 0) nsm = 148;
        cudaFuncSetAttribute(gemm_f16_kernel<0>, cudaFuncAttributeMaxDynamicSharedMemorySize, SMEM_BYTES);
        cudaFuncSetAttribute(gemm_f16_kernel<1>, cudaFuncAttributeMaxDynamicSharedMemorySize, SMEM_BYTES);
    }

    prologue_kernel<<<PRO_BLOCKS, 256>>>(x, router_w, expert_w);
    argmax_kernel<<<1, B_>>>(router_b);

    const int nTilesN = H_ / BNG;                            // 4
    const int nTilesTotal = nTilesN * (N_ / BM) * B_;        // 1024

    // support[b] = x[b] @ expert_w[top1[b]]  -> fp16  (A fp16 cp.async)
    gemm_f16_kernel<0><<<nsm, GT, SMEM_BYTES>>>(
        xh, (long)N_ * H_, H_,
        wh, (long)H_ * H_, H_, 1,
        suph, 0, (long)N_ * H_, H_, H_, nTilesN, nTilesTotal);

    // outh[b] = adj[b] @ support[b]  -> fp16 + fused stats  (A fp32 in-kernel cvt)
    gemm_f16_kernel<1><<<nsm, GT, SMEM_BYTES>>>(
        adj, (long)N_ * N_, N_,
        suph, (long)N_ * H_, H_, 0,
        outh, 1, (long)N_ * H_, H_, N_, nTilesN, nTilesTotal);

    finalize_kernel<<<E_, H_>>>(bn_gamma, bn_beta);

    size_t total4 = (size_t)B_ * N_ * H_ / 4;
    bn_relu_kernel<<<(unsigned)(total4 / 256), 256>>>(out);
}